// round 8
// baseline (speedup 1.0000x reference)
#include <cuda_runtime.h>
#include <math.h>

#define NPTS 500000
#define DIM  64
#define NC   10000
#define TO   128            // 2*64 combined outputs (q|v)
#define BN_EPS 1e-5f

#define PS 68               // x_s row stride (floats), mult of 4
#define JS 132              // w_s row stride (floats), mult of 4

typedef unsigned long long ull;

// ---------------- scratch (device globals: no allocation allowed) ------------
__device__ float    g_v[(size_t)NPTS * DIM];     // 128 MB
__device__ unsigned g_qmax[NC * DIM];            // order-encoded fp32 max
__device__ float    g_qw[NC * DIM];              // Wk^T q[c]
__device__ float    g_qb[NC];                    // q[c] . bk
__device__ float    g_denom[NC];
__device__ float    g_inv[NC];
__device__ float    g_e[NPTS];
__device__ float    g_bnsum[DIM];
__device__ float    g_bnsq[DIM];
__device__ float    g_scale[DIM];
__device__ float    g_shift[DIM];

__device__ __forceinline__ unsigned encf(float f) {
    unsigned u = __float_as_uint(f);
    return (u & 0x80000000u) ? ~u : (u | 0x80000000u);
}
__device__ __forceinline__ float decf(unsigned u) {
    return __uint_as_float((u & 0x80000000u) ? (u & 0x7FFFFFFFu) : ~u);
}
#define ENC_NEG_INF 0x007FFFFFu

// ---------------- packed fp32x2 helpers --------------------------------------
__device__ __forceinline__ ull pack_dup(float x) {
    ull r;
    asm("mov.b64 %0, {%1, %1};" : "=l"(r) : "f"(x));
    return r;
}
__device__ __forceinline__ void unpack2(ull p, float& lo, float& hi) {
    asm("mov.b64 {%0, %1}, %2;" : "=f"(lo), "=f"(hi) : "l"(p));
}
#define FMA_F32X2(d, a, b, c) \
    asm("fma.rn.f32x2 %0, %1, %2, %3;" : "=l"(d) : "l"(a), "l"(b), "l"(c))

// ---------------- K0: init ---------------------------------------------------
__global__ void k_init() {
    int i = blockIdx.x * blockDim.x + threadIdx.x;
    if (i < NC * DIM) g_qmax[i] = ENC_NEG_INF;
    if (i < NC)       g_denom[i] = 0.f;
    if (i < DIM)      { g_bnsum[i] = 0.f; g_bnsq[i] = 0.f; }
}

// ---------------- K1: fused QV GEMM (f32x2) + q segment-max + v store --------
// 128 threads, tile = 64 pts x 128 outs; thread tile 8 pts x 8 outs.
// 2 syncthreads per tile; v stored direct to global from accumulators.
__global__ __launch_bounds__(128, 4)
void k_qv(const float* __restrict__ x, const int* __restrict__ cluster,
          const float* __restrict__ Wv, const float* __restrict__ bv,
          const float* __restrict__ Wq, const float* __restrict__ bq) {
    extern __shared__ float sm[];
    float* w_s = sm;                    // [64][JS]  (transposed: w_s[d][j])
    float* x_s = sm + 64 * JS;          // [64][PS]
    float* b_s = x_s + 64 * PS;         // [128]
    __shared__ int c_s[2][64];          // double-buffered cluster ids

    const int tid = threadIdx.x;
    const int tx  = tid & 15;           // output-group 0..15
    const int ty  = tid >> 4;           // point-group 0..7
    const int j0  = tx * 8;
    const int p0  = ty * 8;

    // weights transposed + biases (once per block)
    for (int l = tid; l < TO * 16; l += 128) {
        int j = l >> 4, dc = l & 15;
        const float* Wsrc = (j < 64) ? Wq : Wv;
        int jr = j & 63;
        float4 wv = *(const float4*)&Wsrc[jr * 64 + dc * 4];
        w_s[(dc * 4 + 0) * JS + j] = wv.x;
        w_s[(dc * 4 + 1) * JS + j] = wv.y;
        w_s[(dc * 4 + 2) * JS + j] = wv.z;
        w_s[(dc * 4 + 3) * JS + j] = wv.w;
    }
    for (int l = tid; l < TO; l += 128)
        b_s[l] = (l < 64) ? bq[l] : bv[l - 64];
    __syncthreads();

    const int numTiles = (NPTS + 63) / 64;
    int buf = 0;
    for (int tile = blockIdx.x; tile < numTiles; tile += gridDim.x, buf ^= 1) {
        const int base = tile * 64;

        // load x tile coalesced
        for (int l = tid; l < 64 * 16; l += 128) {
            int p = l >> 4, ch = l & 15;
            float4 xv = (base + p < NPTS)
                      ? *(const float4*)&x[(size_t)(base + p) * 64 + ch * 4]
                      : make_float4(0.f, 0.f, 0.f, 0.f);
            *(float4*)&x_s[p * PS + ch * 4] = xv;
        }
        if (tid < 64) c_s[buf][tid] = (base + tid < NPTS) ? cluster[base + tid] : 0;
        __syncthreads();

        ull acc[8][4];
        {
            const ull* bp = (const ull*)&b_s[j0];
            #pragma unroll
            for (int m = 0; m < 4; m++) {
                ull bb = bp[m];
                #pragma unroll
                for (int pp = 0; pp < 8; pp++) acc[pp][m] = bb;
            }
        }

        #pragma unroll 4
        for (int d4 = 0; d4 < 16; d4++) {
            float xr[8][4];
            #pragma unroll
            for (int pp = 0; pp < 8; pp++) {
                float4 t = *(const float4*)&x_s[(p0 + pp) * PS + d4 * 4];
                xr[pp][0] = t.x; xr[pp][1] = t.y; xr[pp][2] = t.z; xr[pp][3] = t.w;
            }
            #pragma unroll
            for (int q = 0; q < 4; q++) {
                const int d = d4 * 4 + q;
                const ull* wp = (const ull*)&w_s[d * JS + j0];
                ull wr[4];
                #pragma unroll
                for (int m = 0; m < 4; m++) wr[m] = wp[m];
                #pragma unroll
                for (int pp = 0; pp < 8; pp++) {
                    ull a = pack_dup(xr[pp][q]);
                    #pragma unroll
                    for (int m = 0; m < 4; m++)
                        FMA_F32X2(acc[pp][m], a, wr[m], acc[pp][m]);
                }
            }
        }
        __syncthreads();   // x_s consumed; next iteration may refill it

        if (tx < 8) {
            // q columns: segment max via encoded integer atomicMax
            #pragma unroll
            for (int pp = 0; pp < 8; pp++) {
                const int p = p0 + pp;
                if (base + p < NPTS) {
                    const int cl = c_s[buf][p];
                    #pragma unroll
                    for (int m = 0; m < 4; m++) {
                        float lo, hi;
                        unpack2(acc[pp][m], lo, hi);
                        atomicMax(&g_qmax[cl * 64 + j0 + 2 * m],     encf(lo));
                        atomicMax(&g_qmax[cl * 64 + j0 + 2 * m + 1], encf(hi));
                    }
                }
            }
        } else {
            // v columns: direct float4 stores from accumulators
            const int jv = j0 - 64;
            #pragma unroll
            for (int pp = 0; pp < 8; pp++) {
                const int p = p0 + pp;
                if (base + p < NPTS) {
                    float a0, a1, a2, a3, a4, a5, a6, a7;
                    unpack2(acc[pp][0], a0, a1);
                    unpack2(acc[pp][1], a2, a3);
                    unpack2(acc[pp][2], a4, a5);
                    unpack2(acc[pp][3], a6, a7);
                    float4 t0 = make_float4(a0, a1, a2, a3);
                    float4 t1 = make_float4(a4, a5, a6, a7);
                    float* dst = &g_v[(size_t)(base + p) * 64 + jv];
                    *(float4*)dst       = t0;
                    *(float4*)(dst + 4) = t1;
                }
            }
        }
    }
}

// ---------------- K2: per-cluster transform qw[c] = Wk^T q[c], qb = q.bk -----
__global__ __launch_bounds__(256)
void k_qtrans(const float* __restrict__ Wk, const float* __restrict__ bk) {
    __shared__ float wks[64 * 64];
    __shared__ float qs[4][64];
    __shared__ float bks[64];
    const int tid = threadIdx.x;
    for (int l = tid; l < 64 * 64; l += 256) wks[l] = Wk[l];
    if (tid < 64) bks[tid] = bk[tid];
    const int cl = tid >> 6;
    const int d  = tid & 63;
    const int c  = blockIdx.x * 4 + cl;
    qs[cl][d] = decf(g_qmax[c * 64 + d]);
    __syncthreads();
    float s = 0.f;
    #pragma unroll 8
    for (int j = 0; j < 64; j++)
        s = fmaf(qs[cl][j], wks[j * 64 + d], s);
    g_qw[c * 64 + d] = s;
    if (d == 0) {
        float t = 0.f;
        #pragma unroll 8
        for (int j = 0; j < 64; j++) t = fmaf(qs[cl][j], bks[j], t);
        g_qb[c] = t;
    }
}

// ---------------- K3: fused score + exp + denom ------------------------------
// M bounded (|M| < ~30) so unstabilized exp is safe in fp32.
__global__ void k_score(const float* __restrict__ x,
                        const int* __restrict__ cluster) {
    int t = blockIdx.x * blockDim.x + threadIdx.x;
    int i = t >> 3;
    int r = t & 7;
    if (i >= NPTS) return;
    int cl = cluster[i];
    const float4* xp = (const float4*)&x[(size_t)i * 64];
    const float4* qp = (const float4*)&g_qw[cl * 64];
    float s = 0.f;
    #pragma unroll
    for (int h = 0; h < 2; h++) {
        float4 xv = xp[r + h * 8];
        float4 qv = qp[r + h * 8];
        s += xv.x * qv.x + xv.y * qv.y + xv.z * qv.z + xv.w * qv.w;
    }
    s += __shfl_down_sync(0xFFFFFFFFu, s, 4);
    s += __shfl_down_sync(0xFFFFFFFFu, s, 2);
    s += __shfl_down_sync(0xFFFFFFFFu, s, 1);
    if (r == 0) {
        float e = expf(s + g_qb[cl]);
        g_e[i] = e;
        atomicAdd(&g_denom[cl], e);
    }
}

// ---------------- K4: inv[c] = 1/denom[c] ------------------------------------
__global__ void k_invdenom() {
    int c = blockIdx.x * blockDim.x + threadIdx.x;
    if (c < NC) g_inv[c] = 1.0f / g_denom[c];
}

// ---------------- K5: BN statistics over h = attn * v ------------------------
__global__ void k_bnstats(const int* __restrict__ cluster) {
    const int tid = threadIdx.x;
    const int jj  = tid & 63;
    const int pg  = tid >> 6;
    float s = 0.f, s2 = 0.f;
    for (int i = blockIdx.x * 4 + pg; i < NPTS; i += gridDim.x * 4) {
        float attn = g_e[i] * g_inv[cluster[i]];
        float h = attn * g_v[(size_t)i * 64 + jj];
        s += h; s2 += h * h;
    }
    __shared__ float sh[64], sh2[64];
    if (tid < 64) { sh[tid] = 0.f; sh2[tid] = 0.f; }
    __syncthreads();
    atomicAdd(&sh[jj], s);
    atomicAdd(&sh2[jj], s2);
    __syncthreads();
    if (tid < 64) {
        atomicAdd(&g_bnsum[tid], sh[tid]);
        atomicAdd(&g_bnsq[tid],  sh2[tid]);
    }
}

// ---------------- K6: fold BN into per-column scale/shift --------------------
__global__ void k_bnscale(const float* __restrict__ gamma,
                          const float* __restrict__ beta) {
    int j = threadIdx.x;
    if (j >= DIM) return;
    float mean = g_bnsum[j] / (float)NPTS;
    float var  = g_bnsq[j] / (float)NPTS - mean * mean;
    float sc   = gamma[j] * rsqrtf(var + BN_EPS);
    g_scale[j] = sc;
    g_shift[j] = beta[j] - mean * sc;
}

// ---------------- K7: out = relu(h*scale + shift) ----------------------------
__global__ void k_out(const int* __restrict__ cluster, float* __restrict__ out) {
    int idx = blockIdx.x * blockDim.x + threadIdx.x;
    if (idx >= NPTS * 64) return;
    int i  = idx >> 6;
    int jj = idx & 63;
    float attn = g_e[i] * g_inv[cluster[i]];
    float h = attn * g_v[idx];
    float r = fmaf(h, g_scale[jj], g_shift[jj]);
    out[idx] = fmaxf(r, 0.f);
}

// ---------------- launcher ---------------------------------------------------
extern "C" void kernel_launch(void* const* d_in, const int* in_sizes, int n_in,
                              void* d_out, int out_size) {
    (void)in_sizes; (void)n_in; (void)out_size;
    const float* x       = (const float*)d_in[1];
    const int*   cluster = (const int*)  d_in[2];
    const float* Wv      = (const float*)d_in[3];
    const float* bv      = (const float*)d_in[4];
    const float* Wk      = (const float*)d_in[5];
    const float* bk      = (const float*)d_in[6];
    const float* Wq      = (const float*)d_in[7];
    const float* bq      = (const float*)d_in[8];
    const float* gamma   = (const float*)d_in[9];
    const float* beta    = (const float*)d_in[10];
    float* out = (float*)d_out;

    k_init<<<(NC * DIM + 255) / 256, 256>>>();

    size_t smem = (size_t)(64 * JS + 64 * PS + TO) * sizeof(float);
    cudaFuncSetAttribute(k_qv, cudaFuncAttributeMaxDynamicSharedMemorySize,
                         (int)smem);
    k_qv<<<592, 128, smem>>>(x, cluster, Wv, bv, Wq, bq);

    k_qtrans<<<NC / 4, 256>>>(Wk, bk);
    k_score<<<(NPTS * 8 + 255) / 256, 256>>>(x, cluster);
    k_invdenom<<<(NC + 255) / 256, 256>>>();
    k_bnstats<<<1184, 256>>>(cluster);
    k_bnscale<<<1, 64>>>(gamma, beta);
    k_out<<<(NPTS * 64 + 255) / 256, 256>>>(cluster, out);
}

// round 9
// speedup vs baseline: 1.1092x; 1.1092x over previous
#include <cuda_runtime.h>
#include <math.h>

#define NPTS 500000
#define DIM  64
#define NC   10000
#define TO   128            // 2*64 combined outputs (q|v)
#define BN_EPS 1e-5f

#define PS 68               // x_s row stride (floats), mult of 4
#define JS 132              // w_s row stride (floats), mult of 4

typedef unsigned long long ull;

// ---------------- scratch (device globals: no allocation allowed) ------------
__device__ float    g_v[(size_t)NPTS * DIM];     // 128 MB
__device__ unsigned g_qmax[NC * DIM];            // order-encoded fp32 max
__device__ float    g_qw[NC * DIM];              // Wk^T q[c]
__device__ float    g_qb[NC];                    // q[c] . bk
__device__ float    g_denom[NC];
__device__ float    g_inv[NC];
__device__ float    g_e[NPTS];
__device__ float    g_bnsum[DIM];
__device__ float    g_bnsq[DIM];
__device__ float    g_scale[DIM];
__device__ float    g_shift[DIM];

__device__ __forceinline__ unsigned encf(float f) {
    unsigned u = __float_as_uint(f);
    return (u & 0x80000000u) ? ~u : (u | 0x80000000u);
}
__device__ __forceinline__ float decf(unsigned u) {
    return __uint_as_float((u & 0x80000000u) ? (u & 0x7FFFFFFFu) : ~u);
}
#define ENC_NEG_INF 0x007FFFFFu

// ---------------- packed fp32x2 helpers --------------------------------------
__device__ __forceinline__ ull pack_dup(float x) {
    ull r;
    asm("mov.b64 %0, {%1, %1};" : "=l"(r) : "f"(x));
    return r;
}
__device__ __forceinline__ void unpack2(ull p, float& lo, float& hi) {
    asm("mov.b64 {%0, %1}, %2;" : "=f"(lo), "=f"(hi) : "l"(p));
}
#define FMA_F32X2(d, a, b, c) \
    asm("fma.rn.f32x2 %0, %1, %2, %3;" : "=l"(d) : "l"(a), "l"(b), "l"(c))

// ---------------- K0: init ---------------------------------------------------
__global__ void k_init() {
    int i = blockIdx.x * blockDim.x + threadIdx.x;
    if (i < NC * DIM) g_qmax[i] = ENC_NEG_INF;
    if (i < NC)       g_denom[i] = 0.f;
    if (i < DIM)      { g_bnsum[i] = 0.f; g_bnsq[i] = 0.f; }
}

// ---------------- K1: fused QV GEMM (f32x2) + filtered q seg-max + v store ---
// 128 threads, tile = 64 pts x 128 outs; thread tile 8 pts x 8 outs.
// q segment-max uses read-then-atomic filtering (monotone max => race-safe):
// expected atomic lanes drop ~12x vs unconditional RED.MAX.
__global__ __launch_bounds__(128, 4)
void k_qv(const float* __restrict__ x, const int* __restrict__ cluster,
          const float* __restrict__ Wv, const float* __restrict__ bv,
          const float* __restrict__ Wq, const float* __restrict__ bq) {
    extern __shared__ float sm[];
    float* w_s = sm;                    // [64][JS]  (transposed: w_s[d][j])
    float* x_s = sm + 64 * JS;          // [64][PS]
    float* b_s = x_s + 64 * PS;         // [128]
    __shared__ int c_s[2][64];          // double-buffered cluster ids

    const int tid = threadIdx.x;
    const int tx  = tid & 15;           // output-group 0..15
    const int ty  = tid >> 4;           // point-group 0..7
    const int j0  = tx * 8;
    const int p0  = ty * 8;

    // weights transposed + biases (once per block)
    for (int l = tid; l < TO * 16; l += 128) {
        int j = l >> 4, dc = l & 15;
        const float* Wsrc = (j < 64) ? Wq : Wv;
        int jr = j & 63;
        float4 wv = *(const float4*)&Wsrc[jr * 64 + dc * 4];
        w_s[(dc * 4 + 0) * JS + j] = wv.x;
        w_s[(dc * 4 + 1) * JS + j] = wv.y;
        w_s[(dc * 4 + 2) * JS + j] = wv.z;
        w_s[(dc * 4 + 3) * JS + j] = wv.w;
    }
    for (int l = tid; l < TO; l += 128)
        b_s[l] = (l < 64) ? bq[l] : bv[l - 64];
    __syncthreads();

    const int numTiles = (NPTS + 63) / 64;
    int buf = 0;
    for (int tile = blockIdx.x; tile < numTiles; tile += gridDim.x, buf ^= 1) {
        const int base = tile * 64;

        // load x tile coalesced
        for (int l = tid; l < 64 * 16; l += 128) {
            int p = l >> 4, ch = l & 15;
            float4 xv = (base + p < NPTS)
                      ? *(const float4*)&x[(size_t)(base + p) * 64 + ch * 4]
                      : make_float4(0.f, 0.f, 0.f, 0.f);
            *(float4*)&x_s[p * PS + ch * 4] = xv;
        }
        if (tid < 64) c_s[buf][tid] = (base + tid < NPTS) ? cluster[base + tid] : 0;
        __syncthreads();

        ull acc[8][4];
        {
            const ull* bp = (const ull*)&b_s[j0];
            #pragma unroll
            for (int m = 0; m < 4; m++) {
                ull bb = bp[m];
                #pragma unroll
                for (int pp = 0; pp < 8; pp++) acc[pp][m] = bb;
            }
        }

        #pragma unroll 4
        for (int d4 = 0; d4 < 16; d4++) {
            float xr[8][4];
            #pragma unroll
            for (int pp = 0; pp < 8; pp++) {
                float4 t = *(const float4*)&x_s[(p0 + pp) * PS + d4 * 4];
                xr[pp][0] = t.x; xr[pp][1] = t.y; xr[pp][2] = t.z; xr[pp][3] = t.w;
            }
            #pragma unroll
            for (int q = 0; q < 4; q++) {
                const int d = d4 * 4 + q;
                const ull* wp = (const ull*)&w_s[d * JS + j0];
                ull wr[4];
                #pragma unroll
                for (int m = 0; m < 4; m++) wr[m] = wp[m];
                #pragma unroll
                for (int pp = 0; pp < 8; pp++) {
                    ull a = pack_dup(xr[pp][q]);
                    #pragma unroll
                    for (int m = 0; m < 4; m++)
                        FMA_F32X2(acc[pp][m], a, wr[m], acc[pp][m]);
                }
            }
        }
        __syncthreads();   // x_s consumed; next iteration may refill it

        if (tx < 8) {
            // q columns: filtered segment max.
            // Cached read is <= coherent L2 value (monotone increase), so a
            // skip is always provably redundant; extra atomics are harmless.
            #pragma unroll
            for (int pp = 0; pp < 8; pp++) {
                const int p = p0 + pp;
                if (base + p < NPTS) {
                    const int cl = c_s[buf][p];
                    const uint4* gp = (const uint4*)&g_qmax[cl * 64 + j0];
                    uint4 c0 = __ldg(gp);
                    uint4 c1 = __ldg(gp + 1);
                    unsigned cur[8] = {c0.x, c0.y, c0.z, c0.w,
                                       c1.x, c1.y, c1.z, c1.w};
                    #pragma unroll
                    for (int m = 0; m < 4; m++) {
                        float lo, hi;
                        unpack2(acc[pp][m], lo, hi);
                        unsigned elo = encf(lo), ehi = encf(hi);
                        if (elo > cur[2 * m])
                            atomicMax(&g_qmax[cl * 64 + j0 + 2 * m], elo);
                        if (ehi > cur[2 * m + 1])
                            atomicMax(&g_qmax[cl * 64 + j0 + 2 * m + 1], ehi);
                    }
                }
            }
        } else {
            // v columns: direct float4 stores from accumulators
            const int jv = j0 - 64;
            #pragma unroll
            for (int pp = 0; pp < 8; pp++) {
                const int p = p0 + pp;
                if (base + p < NPTS) {
                    float a0, a1, a2, a3, a4, a5, a6, a7;
                    unpack2(acc[pp][0], a0, a1);
                    unpack2(acc[pp][1], a2, a3);
                    unpack2(acc[pp][2], a4, a5);
                    unpack2(acc[pp][3], a6, a7);
                    float4 t0 = make_float4(a0, a1, a2, a3);
                    float4 t1 = make_float4(a4, a5, a6, a7);
                    float* dst = &g_v[(size_t)(base + p) * 64 + jv];
                    *(float4*)dst       = t0;
                    *(float4*)(dst + 4) = t1;
                }
            }
        }
    }
}

// ---------------- K2: per-cluster transform qw[c] = Wk^T q[c], qb = q.bk -----
__global__ __launch_bounds__(256)
void k_qtrans(const float* __restrict__ Wk, const float* __restrict__ bk) {
    __shared__ float wks[64 * 64];
    __shared__ float qs[4][64];
    __shared__ float bks[64];
    const int tid = threadIdx.x;
    for (int l = tid; l < 64 * 64; l += 256) wks[l] = Wk[l];
    if (tid < 64) bks[tid] = bk[tid];
    const int cl = tid >> 6;
    const int d  = tid & 63;
    const int c  = blockIdx.x * 4 + cl;
    qs[cl][d] = decf(g_qmax[c * 64 + d]);
    __syncthreads();
    float s = 0.f;
    #pragma unroll 8
    for (int j = 0; j < 64; j++)
        s = fmaf(qs[cl][j], wks[j * 64 + d], s);
    g_qw[c * 64 + d] = s;
    if (d == 0) {
        float t = 0.f;
        #pragma unroll 8
        for (int j = 0; j < 64; j++) t = fmaf(qs[cl][j], bks[j], t);
        g_qb[c] = t;
    }
}

// ---------------- K3: fused score + exp + denom ------------------------------
// M bounded (|M| < ~30) so unstabilized exp is safe in fp32.
__global__ void k_score(const float* __restrict__ x,
                        const int* __restrict__ cluster) {
    int t = blockIdx.x * blockDim.x + threadIdx.x;
    int i = t >> 3;
    int r = t & 7;
    if (i >= NPTS) return;
    int cl = cluster[i];
    const float4* xp = (const float4*)&x[(size_t)i * 64];
    const float4* qp = (const float4*)&g_qw[cl * 64];
    float s = 0.f;
    #pragma unroll
    for (int h = 0; h < 2; h++) {
        float4 xv = xp[r + h * 8];
        float4 qv = qp[r + h * 8];
        s += xv.x * qv.x + xv.y * qv.y + xv.z * qv.z + xv.w * qv.w;
    }
    s += __shfl_down_sync(0xFFFFFFFFu, s, 4);
    s += __shfl_down_sync(0xFFFFFFFFu, s, 2);
    s += __shfl_down_sync(0xFFFFFFFFu, s, 1);
    if (r == 0) {
        float e = expf(s + g_qb[cl]);
        g_e[i] = e;
        atomicAdd(&g_denom[cl], e);
    }
}

// ---------------- K4: inv[c] = 1/denom[c] ------------------------------------
__global__ void k_invdenom() {
    int c = blockIdx.x * blockDim.x + threadIdx.x;
    if (c < NC) g_inv[c] = 1.0f / g_denom[c];
}

// ---------------- K5: BN statistics over h = attn * v ------------------------
__global__ void k_bnstats(const int* __restrict__ cluster) {
    const int tid = threadIdx.x;
    const int jj  = tid & 63;
    const int pg  = tid >> 6;
    float s = 0.f, s2 = 0.f;
    for (int i = blockIdx.x * 4 + pg; i < NPTS; i += gridDim.x * 4) {
        float attn = g_e[i] * g_inv[cluster[i]];
        float h = attn * g_v[(size_t)i * 64 + jj];
        s += h; s2 += h * h;
    }
    __shared__ float sh[64], sh2[64];
    if (tid < 64) { sh[tid] = 0.f; sh2[tid] = 0.f; }
    __syncthreads();
    atomicAdd(&sh[jj], s);
    atomicAdd(&sh2[jj], s2);
    __syncthreads();
    if (tid < 64) {
        atomicAdd(&g_bnsum[tid], sh[tid]);
        atomicAdd(&g_bnsq[tid],  sh2[tid]);
    }
}

// ---------------- K6: fold BN into per-column scale/shift --------------------
__global__ void k_bnscale(const float* __restrict__ gamma,
                          const float* __restrict__ beta) {
    int j = threadIdx.x;
    if (j >= DIM) return;
    float mean = g_bnsum[j] / (float)NPTS;
    float var  = g_bnsq[j] / (float)NPTS - mean * mean;
    float sc   = gamma[j] * rsqrtf(var + BN_EPS);
    g_scale[j] = sc;
    g_shift[j] = beta[j] - mean * sc;
}

// ---------------- K7: out = relu(h*scale + shift) ----------------------------
__global__ void k_out(const int* __restrict__ cluster, float* __restrict__ out) {
    int idx = blockIdx.x * blockDim.x + threadIdx.x;
    if (idx >= NPTS * 64) return;
    int i  = idx >> 6;
    int jj = idx & 63;
    float attn = g_e[i] * g_inv[cluster[i]];
    float h = attn * g_v[idx];
    float r = fmaf(h, g_scale[jj], g_shift[jj]);
    out[idx] = fmaxf(r, 0.f);
}

// ---------------- launcher ---------------------------------------------------
extern "C" void kernel_launch(void* const* d_in, const int* in_sizes, int n_in,
                              void* d_out, int out_size) {
    (void)in_sizes; (void)n_in; (void)out_size;
    const float* x       = (const float*)d_in[1];
    const int*   cluster = (const int*)  d_in[2];
    const float* Wv      = (const float*)d_in[3];
    const float* bv      = (const float*)d_in[4];
    const float* Wk      = (const float*)d_in[5];
    const float* bk      = (const float*)d_in[6];
    const float* Wq      = (const float*)d_in[7];
    const float* bq      = (const float*)d_in[8];
    const float* gamma   = (const float*)d_in[9];
    const float* beta    = (const float*)d_in[10];
    float* out = (float*)d_out;

    k_init<<<(NC * DIM + 255) / 256, 256>>>();

    size_t smem = (size_t)(64 * JS + 64 * PS + TO) * sizeof(float);
    cudaFuncSetAttribute(k_qv, cudaFuncAttributeMaxDynamicSharedMemorySize,
                         (int)smem);
    k_qv<<<592, 128, smem>>>(x, cluster, Wv, bv, Wq, bq);

    k_qtrans<<<NC / 4, 256>>>(Wk, bk);
    k_score<<<(NPTS * 8 + 255) / 256, 256>>>(x, cluster);
    k_invdenom<<<(NC + 255) / 256, 256>>>();
    k_bnstats<<<1184, 256>>>(cluster);
    k_bnscale<<<1, 64>>>(gamma, beta);
    k_out<<<(NPTS * 64 + 255) / 256, 256>>>(cluster, out);
}

// round 11
// speedup vs baseline: 1.3346x; 1.2032x over previous
#include <cuda_runtime.h>
#include <math.h>

#define NPTS 500000
#define DIM  64
#define NC   10000
#define TO   128            // 2*64 combined outputs (q|v)
#define BN_EPS 1e-5f

#define PS 68               // x_s row stride (floats), mult of 4
#define JS 136              // w_s row stride (floats) — swizzled layout

typedef unsigned long long ull;

// ---------------- scratch (device globals: no allocation allowed) ------------
__device__ float    g_v[(size_t)NPTS * DIM];     // 128 MB
__device__ unsigned g_qmax[NC * DIM];            // order-encoded fp32 max
__device__ float    g_qw[NC * DIM];              // Wk^T q[c]
__device__ float    g_qb[NC];                    // q[c] . bk
__device__ float    g_denom[NC];
__device__ float    g_inv[NC];
__device__ float    g_e[NPTS];
__device__ float    g_bnsum[DIM];
__device__ float    g_bnsq[DIM];
__device__ float    g_scale[DIM];
__device__ float    g_shift[DIM];

__device__ __forceinline__ unsigned encf(float f) {
    unsigned u = __float_as_uint(f);
    return (u & 0x80000000u) ? ~u : (u | 0x80000000u);
}
__device__ __forceinline__ float decf(unsigned u) {
    return __uint_as_float((u & 0x80000000u) ? (u & 0x7FFFFFFFu) : ~u);
}
#define ENC_NEG_INF 0x007FFFFFu

// ---------------- packed fp32x2 helpers --------------------------------------
__device__ __forceinline__ ull pack_dup(float x) {
    ull r;
    asm("mov.b64 %0, {%1, %1};" : "=l"(r) : "f"(x));
    return r;
}
__device__ __forceinline__ void unpack2(ull p, float& lo, float& hi) {
    asm("mov.b64 {%0, %1}, %2;" : "=f"(lo), "=f"(hi) : "l"(p));
}
#define FMA_F32X2(d, a, b, c) \
    asm("fma.rn.f32x2 %0, %1, %2, %3;" : "=l"(d) : "l"(a), "l"(b), "l"(c))

// Bank swizzle for w_s columns: j -> j + 2*(j>>5).
// Warp load addrs (8*tx + 2*(tx>>2)) hit 16 distinct bank pairs: conflict-free.
__device__ __forceinline__ int jsw(int j) { return j + ((j >> 5) << 1); }

// ---------------- K0a/b/c: init (split so k_qv is launch #4 for ncu) ---------
__global__ void k_init_qmax() {
    int i = blockIdx.x * blockDim.x + threadIdx.x;
    if (i < NC * DIM) g_qmax[i] = ENC_NEG_INF;
}
__global__ void k_init_denom() {
    int i = blockIdx.x * blockDim.x + threadIdx.x;
    if (i < NC) g_denom[i] = 0.f;
}
__global__ void k_init_bn() {
    int i = threadIdx.x;
    if (i < DIM) { g_bnsum[i] = 0.f; g_bnsq[i] = 0.f; }
}

// ---------------- K1: fused QV GEMM (f32x2) + filtered q seg-max + v store ---
__global__ __launch_bounds__(128, 4)
void k_qv(const float* __restrict__ x, const int* __restrict__ cluster,
          const float* __restrict__ Wv, const float* __restrict__ bv,
          const float* __restrict__ Wq, const float* __restrict__ bq) {
    extern __shared__ float sm[];
    float* w_s = sm;                    // [64][JS]  swizzled (w_s[d][jsw(j)])
    float* x_s = sm + 64 * JS;          // [64][PS]
    float* b_s = x_s + 64 * PS;         // [128]
    __shared__ int c_s[2][64];

    const int tid = threadIdx.x;
    const int tx  = tid & 15;           // output-group 0..15
    const int ty  = tid >> 4;           // point-group 0..7
    const int j0  = tx * 8;
    const int p0  = ty * 8;
    const int jofs = j0 + ((tx >> 2) << 1);   // swizzled load base

    // weights transposed + biases (once per block)
    for (int l = tid; l < TO * 16; l += 128) {
        int j = l >> 4, dc = l & 15;
        const float* Wsrc = (j < 64) ? Wq : Wv;
        int jr = j & 63;
        float4 wv = *(const float4*)&Wsrc[jr * 64 + dc * 4];
        int js = jsw(j);
        w_s[(dc * 4 + 0) * JS + js] = wv.x;
        w_s[(dc * 4 + 1) * JS + js] = wv.y;
        w_s[(dc * 4 + 2) * JS + js] = wv.z;
        w_s[(dc * 4 + 3) * JS + js] = wv.w;
    }
    for (int l = tid; l < TO; l += 128)
        b_s[l] = (l < 64) ? bq[l] : bv[l - 64];
    __syncthreads();

    const int numTiles = (NPTS + 63) / 64;
    int buf = 0;
    for (int tile = blockIdx.x; tile < numTiles; tile += gridDim.x, buf ^= 1) {
        const int base = tile * 64;

        for (int l = tid; l < 64 * 16; l += 128) {
            int p = l >> 4, ch = l & 15;
            float4 xv = (base + p < NPTS)
                      ? *(const float4*)&x[(size_t)(base + p) * 64 + ch * 4]
                      : make_float4(0.f, 0.f, 0.f, 0.f);
            *(float4*)&x_s[p * PS + ch * 4] = xv;
        }
        if (tid < 64) c_s[buf][tid] = (base + tid < NPTS) ? cluster[base + tid] : 0;
        __syncthreads();

        ull acc[8][4];
        {
            const ull* bp = (const ull*)&b_s[j0];
            #pragma unroll
            for (int m = 0; m < 4; m++) {
                ull bb = bp[m];
                #pragma unroll
                for (int pp = 0; pp < 8; pp++) acc[pp][m] = bb;
            }
        }

        #pragma unroll 4
        for (int d4 = 0; d4 < 16; d4++) {
            float xr[8][4];
            #pragma unroll
            for (int pp = 0; pp < 8; pp++) {
                float4 t = *(const float4*)&x_s[(p0 + pp) * PS + d4 * 4];
                xr[pp][0] = t.x; xr[pp][1] = t.y; xr[pp][2] = t.z; xr[pp][3] = t.w;
            }
            #pragma unroll
            for (int q = 0; q < 4; q++) {
                const int d = d4 * 4 + q;
                const ull* wp = (const ull*)&w_s[d * JS + jofs];
                ull wr[4];
                #pragma unroll
                for (int m = 0; m < 4; m++) wr[m] = wp[m];
                #pragma unroll
                for (int pp = 0; pp < 8; pp++) {
                    ull a = pack_dup(xr[pp][q]);
                    #pragma unroll
                    for (int m = 0; m < 4; m++)
                        FMA_F32X2(acc[pp][m], a, wr[m], acc[pp][m]);
                }
            }
        }
        __syncthreads();

        if (tx < 8) {
            // q columns: filtered segment max (monotone => race-safe precheck)
            #pragma unroll
            for (int pp = 0; pp < 8; pp++) {
                const int p = p0 + pp;
                if (base + p < NPTS) {
                    const int cl = c_s[buf][p];
                    const uint4* gp = (const uint4*)&g_qmax[cl * 64 + j0];
                    uint4 c0 = __ldg(gp);
                    uint4 c1 = __ldg(gp + 1);
                    unsigned cur[8] = {c0.x, c0.y, c0.z, c0.w,
                                       c1.x, c1.y, c1.z, c1.w};
                    #pragma unroll
                    for (int m = 0; m < 4; m++) {
                        float lo, hi;
                        unpack2(acc[pp][m], lo, hi);
                        unsigned elo = encf(lo), ehi = encf(hi);
                        if (elo > cur[2 * m])
                            atomicMax(&g_qmax[cl * 64 + j0 + 2 * m], elo);
                        if (ehi > cur[2 * m + 1])
                            atomicMax(&g_qmax[cl * 64 + j0 + 2 * m + 1], ehi);
                    }
                }
            }
        } else {
            // v columns: direct float4 stores from accumulators
            const int jv = j0 - 64;
            #pragma unroll
            for (int pp = 0; pp < 8; pp++) {
                const int p = p0 + pp;
                if (base + p < NPTS) {
                    float a0, a1, a2, a3, a4, a5, a6, a7;
                    unpack2(acc[pp][0], a0, a1);
                    unpack2(acc[pp][1], a2, a3);
                    unpack2(acc[pp][2], a4, a5);
                    unpack2(acc[pp][3], a6, a7);
                    float4 t0 = make_float4(a0, a1, a2, a3);
                    float4 t1 = make_float4(a4, a5, a6, a7);
                    float* dst = &g_v[(size_t)(base + p) * 64 + jv];
                    *(float4*)dst       = t0;
                    *(float4*)(dst + 4) = t1;
                }
            }
        }
    }
}

// ---------------- K2: per-cluster transform qw[c] = Wk^T q[c], qb = q.bk -----
__global__ __launch_bounds__(256)
void k_qtrans(const float* __restrict__ Wk, const float* __restrict__ bk) {
    __shared__ float wks[64 * 64];
    __shared__ float qs[4][64];
    __shared__ float bks[64];
    const int tid = threadIdx.x;
    for (int l = tid; l < 64 * 64; l += 256) wks[l] = Wk[l];
    if (tid < 64) bks[tid] = bk[tid];
    const int cl = tid >> 6;
    const int d  = tid & 63;
    const int c  = blockIdx.x * 4 + cl;
    qs[cl][d] = decf(g_qmax[c * 64 + d]);
    __syncthreads();
    float s = 0.f;
    #pragma unroll 8
    for (int j = 0; j < 64; j++)
        s = fmaf(qs[cl][j], wks[j * 64 + d], s);
    g_qw[c * 64 + d] = s;
    if (d == 0) {
        float t = 0.f;
        #pragma unroll 8
        for (int j = 0; j < 64; j++) t = fmaf(qs[cl][j], bks[j], t);
        g_qb[c] = t;
    }
}

// ---------------- K3: fused score + exp + denom ------------------------------
__global__ void k_score(const float* __restrict__ x,
                        const int* __restrict__ cluster) {
    int t = blockIdx.x * blockDim.x + threadIdx.x;
    int i = t >> 3;
    int r = t & 7;
    if (i >= NPTS) return;
    int cl = cluster[i];
    const float4* xp = (const float4*)&x[(size_t)i * 64];
    const float4* qp = (const float4*)&g_qw[cl * 64];
    float s = 0.f;
    #pragma unroll
    for (int h = 0; h < 2; h++) {
        float4 xv = xp[r + h * 8];
        float4 qv = qp[r + h * 8];
        s += xv.x * qv.x + xv.y * qv.y + xv.z * qv.z + xv.w * qv.w;
    }
    s += __shfl_down_sync(0xFFFFFFFFu, s, 4);
    s += __shfl_down_sync(0xFFFFFFFFu, s, 2);
    s += __shfl_down_sync(0xFFFFFFFFu, s, 1);
    if (r == 0) {
        float e = expf(s + g_qb[cl]);
        g_e[i] = e;
        atomicAdd(&g_denom[cl], e);
    }
}

// ---------------- K4: inv[c] = 1/denom[c] ------------------------------------
__global__ void k_invdenom() {
    int c = blockIdx.x * blockDim.x + threadIdx.x;
    if (c < NC) g_inv[c] = 1.0f / g_denom[c];
}

// ---------------- K5: BN statistics over h = attn * v ------------------------
__global__ void k_bnstats(const int* __restrict__ cluster) {
    const int tid = threadIdx.x;
    const int jj  = tid & 63;
    const int pg  = tid >> 6;
    float s = 0.f, s2 = 0.f;
    for (int i = blockIdx.x * 4 + pg; i < NPTS; i += gridDim.x * 4) {
        float attn = g_e[i] * g_inv[cluster[i]];
        float h = attn * g_v[(size_t)i * 64 + jj];
        s += h; s2 += h * h;
    }
    __shared__ float sh[64], sh2[64];
    if (tid < 64) { sh[tid] = 0.f; sh2[tid] = 0.f; }
    __syncthreads();
    atomicAdd(&sh[jj], s);
    atomicAdd(&sh2[jj], s2);
    __syncthreads();
    if (tid < 64) {
        atomicAdd(&g_bnsum[tid], sh[tid]);
        atomicAdd(&g_bnsq[tid],  sh2[tid]);
    }
}

// ---------------- K6: fold BN into per-column scale/shift --------------------
__global__ void k_bnscale(const float* __restrict__ gamma,
                          const float* __restrict__ beta) {
    int j = threadIdx.x;
    if (j >= DIM) return;
    float mean = g_bnsum[j] / (float)NPTS;
    float var  = g_bnsq[j] / (float)NPTS - mean * mean;
    float sc   = gamma[j] * rsqrtf(var + BN_EPS);
    g_scale[j] = sc;
    g_shift[j] = beta[j] - mean * sc;
}

// ---------------- K7: out = relu(h*scale + shift), float4 ---------------------
__global__ void k_out(const int* __restrict__ cluster, float* __restrict__ out) {
    int idx = blockIdx.x * blockDim.x + threadIdx.x;   // over float4s
    if (idx >= NPTS * 16) return;
    int i  = idx >> 4;
    int j4 = (idx & 15) * 4;
    float attn = g_e[i] * g_inv[cluster[i]];
    float4 v = *(const float4*)&g_v[(size_t)i * 64 + j4];
    float4 r;
    r.x = fmaxf(fmaf(attn * v.x, g_scale[j4 + 0], g_shift[j4 + 0]), 0.f);
    r.y = fmaxf(fmaf(attn * v.y, g_scale[j4 + 1], g_shift[j4 + 1]), 0.f);
    r.z = fmaxf(fmaf(attn * v.z, g_scale[j4 + 2], g_shift[j4 + 2]), 0.f);
    r.w = fmaxf(fmaf(attn * v.w, g_scale[j4 + 3], g_shift[j4 + 3]), 0.f);
    *(float4*)&out[(size_t)i * 64 + j4] = r;
}

// ---------------- launcher ---------------------------------------------------
extern "C" void kernel_launch(void* const* d_in, const int* in_sizes, int n_in,
                              void* d_out, int out_size) {
    (void)in_sizes; (void)n_in; (void)out_size;
    const float* x       = (const float*)d_in[1];
    const int*   cluster = (const int*)  d_in[2];
    const float* Wv      = (const float*)d_in[3];
    const float* bv      = (const float*)d_in[4];
    const float* Wk      = (const float*)d_in[5];
    const float* bk      = (const float*)d_in[6];
    const float* Wq      = (const float*)d_in[7];
    const float* bq      = (const float*)d_in[8];
    const float* gamma   = (const float*)d_in[9];
    const float* beta    = (const float*)d_in[10];
    float* out = (float*)d_out;

    k_init_qmax<<<(NC * DIM + 255) / 256, 256>>>();
    k_init_denom<<<(NC + 255) / 256, 256>>>();
    k_init_bn<<<1, 64>>>();

    size_t smem = (size_t)(64 * JS + 64 * PS + TO) * sizeof(float);
    cudaFuncSetAttribute(k_qv, cudaFuncAttributeMaxDynamicSharedMemorySize,
                         (int)smem);
    k_qv<<<592, 128, smem>>>(x, cluster, Wv, bv, Wq, bq);

    k_qtrans<<<NC / 4, 256>>>(Wk, bk);
    k_score<<<(NPTS * 8 + 255) / 256, 256>>>(x, cluster);
    k_invdenom<<<(NC + 255) / 256, 256>>>();
    k_bnstats<<<1184, 256>>>(cluster);
    k_bnscale<<<1, 64>>>(gamma, beta);
    k_out<<<(NPTS * 16 + 255) / 256, 256>>>(cluster, out);
}